// round 1
// baseline (speedup 1.0000x reference)
#include <cuda_runtime.h>
#include <math.h>

#define N_NODES 16384
#define C_DIM   64
#define KNN     40
#define NPARTS  2
#define HALF    8192
#define TILE    2048
#define BUF     28
#define KNN_T   64
#define BN_EPS  1e-5f
#define FBIG    1e30f

// ---------------- scratch (static device globals; no allocation) ----------------
__device__ float4 g_s4[N_NODES];                    // learned coords, padded to float4
__device__ float  g_h[N_NODES * C_DIM];             // propagated features
__device__ float  g_partD[NPARTS * KNN * N_NODES];  // [part*K + j][N] partial top-K dists
__device__ int    g_partI[NPARTS * KNN * N_NODES];  // matching indices
__device__ int    g_idx[KNN * N_NODES];             // final [K][N] neighbor idx
__device__ float  g_ew[KNN * N_NODES];              // final [K][N] edge weights
__device__ float  g_t[N_NODES * C_DIM];             // xgn + x (pre-BN2)
__device__ float  g_wres[N_NODES * C_DIM];          // y + z (pre-BN3)
__device__ float  g_mu2[C_DIM], g_rs2[C_DIM], g_mu3[C_DIM], g_rs3[C_DIM];

// ---------------- K1: h = x@w_h + b_h ; s = x@w_s ----------------
__global__ __launch_bounds__(512) void k_prep(const float* __restrict__ x,
                                              const float* __restrict__ w_h,
                                              const float* __restrict__ b_h,
                                              const float* __restrict__ w_s) {
    __shared__ float whs[C_DIM * C_DIM];   // 16KB
    __shared__ float wss[C_DIM * 4];       // padded [64][4]
    __shared__ float sx[8][C_DIM];         // 2KB
    int tid = threadIdx.x;
    for (int i = tid; i < C_DIM * C_DIM; i += 512) whs[i] = w_h[i];
    if (tid < C_DIM * 3) wss[(tid / 3) * 4 + (tid % 3)] = w_s[tid];
    int g = tid >> 6, c = tid & 63;
    int n = blockIdx.x * 8 + g;
    sx[g][c] = x[n * C_DIM + c];
    __syncthreads();
    float acc = b_h[c];
#pragma unroll
    for (int k2 = 0; k2 < C_DIM; k2++) acc = fmaf(sx[g][k2], whs[k2 * C_DIM + c], acc);
    g_h[n * C_DIM + c] = acc;
    if (c < 4) {
        float sv = 0.f;
        if (c < 3) {
#pragma unroll
            for (int k2 = 0; k2 < C_DIM; k2++) sv = fmaf(sx[g][k2], wss[k2 * 4 + c], sv);
        }
        ((float*)g_s4)[n * 4 + c] = sv;
    }
}

// ---------------- K2: kNN (partitioned candidate scan, buffered insert) ----------------
__device__ __forceinline__ void insert40(float (&bd)[KNN], int (&bi)[KNN],
                                         float cd, int ci, bool want) {
    // ascending list; bd[KNN-1] is the current worst. Bubble cd down from the worst end.
    bool placed = !want;
#pragma unroll
    for (int j = KNN - 1; j >= 1; j--) {
        if (!placed) {
            bool sw = cd < bd[j - 1];
            float pu = bd[j - 1];
            int   iu = bi[j - 1];
            bd[j] = sw ? pu : cd;
            bi[j] = sw ? iu : ci;
            placed = !sw;
        }
        if ((j & 7) == 0) {
            if (__all_sync(0xffffffffu, placed)) return;
        }
    }
    if (!placed) { bd[0] = cd; bi[0] = ci; }
}

__global__ __launch_bounds__(KNN_T) void k_knn() {
    __shared__ float4 shp[TILE];           // 32KB candidate tile
    __shared__ float  bufD[KNN_T][BUF];    // 7KB deferred candidates
    __shared__ int    bufI[KNN_T][BUF];    // 7KB
    int tid = threadIdx.x;
    int q = blockIdx.x * KNN_T + tid;
    int base0 = blockIdx.y * HALF;
    float4 qs = g_s4[q];
    float bd[KNN]; int bi[KNN];
#pragma unroll
    for (int j = 0; j < KNN; j++) { bd[j] = FBIG; bi[j] = 0; }
    int cnt = 0;

    for (int t0 = 0; t0 < HALF; t0 += TILE) {
        for (int j = tid; j < TILE; j += KNN_T) shp[j] = g_s4[base0 + t0 + j];
        __syncthreads();
        for (int j = 0; j < TILE; j += 4) {
#pragma unroll
            for (int u = 0; u < 4; u++) {
                float4 p = shp[j + u];
                float dx = qs.x - p.x, dy = qs.y - p.y, dz = qs.z - p.z;
                float d2 = fmaf(dx, dx, fmaf(dy, dy, dz * dz));
                if (d2 < bd[KNN - 1]) {
                    bufD[tid][cnt] = d2;
                    bufI[tid][cnt] = base0 + t0 + j + u;
                    cnt++;
                }
            }
            if (__any_sync(0xffffffffu, cnt >= BUF - 4)) {
                int mx = cnt;
#pragma unroll
                for (int o = 16; o > 0; o >>= 1)
                    mx = max(mx, __shfl_xor_sync(0xffffffffu, mx, o));
                for (int e = 0; e < mx; e++) {
                    bool act = e < cnt;
                    float d = act ? bufD[tid][e] : FBIG;
                    int idv = act ? bufI[tid][e] : 0;
                    insert40(bd, bi, d, idv, act && (d < bd[KNN - 1]));
                }
                cnt = 0;
            }
        }
        __syncthreads();
    }
    {   // final flush
        int mx = cnt;
#pragma unroll
        for (int o = 16; o > 0; o >>= 1)
            mx = max(mx, __shfl_xor_sync(0xffffffffu, mx, o));
        for (int e = 0; e < mx; e++) {
            bool act = e < cnt;
            float d = act ? bufD[tid][e] : FBIG;
            int idv = act ? bufI[tid][e] : 0;
            insert40(bd, bi, d, idv, act && (d < bd[KNN - 1]));
        }
    }
    int ob = blockIdx.y * KNN;
#pragma unroll
    for (int j = 0; j < KNN; j++) {
        g_partD[(ob + j) * N_NODES + q] = bd[j];
        g_partI[(ob + j) * N_NODES + q] = bi[j];
    }
}

// ---------------- K2b: merge the 2 partitions' sorted lists; edge weights ----------------
__global__ void k_merge() {
    int q = blockIdx.x * 256 + threadIdx.x;
    int a = 0, b = 0;
#pragma unroll 1
    for (int j = 0; j < KNN; j++) {
        float da = g_partD[a * N_NODES + q];
        float db = g_partD[(KNN + b) * N_NODES + q];
        bool ta = da <= db;                 // ties -> lower-index partition (lower global idx)
        float d = ta ? da : db;
        int idv = ta ? g_partI[a * N_NODES + q] : g_partI[(KNN + b) * N_NODES + q];
        if (ta) a++; else b++;
        g_idx[j * N_NODES + q] = idv;
        g_ew[j * N_NODES + q] = expf(-(d + 1e-6f));
    }
}

// ---------------- K3: gather-aggregate (mean,max) + lin(cat) + residual ----------------
__global__ __launch_bounds__(512) void k_agglin(const float* __restrict__ x,
                                                const float* __restrict__ w_lin,
                                                const float* __restrict__ b_lin) {
    __shared__ float Ws[128 * 64];    // 32KB: rows 0..127 of w_lin (mean,max parts)
    __shared__ float scat[8][128];    // 4KB: per-node [mean|max]
    __shared__ float sx[8][64];       // 2KB: per-node x row
    int tid = threadIdx.x;
    for (int i = tid; i < (128 * 64) / 4; i += 512)
        ((float4*)Ws)[i] = ((const float4*)w_lin)[i];
    int g = tid >> 6, c = tid & 63;
    int n = blockIdx.x * 8 + g;
    float mean = 0.f, mx = -FBIG;
#pragma unroll 1
    for (int k2 = 0; k2 < KNN; k2++) {
        int i = g_idx[k2 * N_NODES + n];
        float w = g_ew[k2 * N_NODES + n];
        float m = w * g_h[i * C_DIM + c];
        mean += m;
        mx = fmaxf(mx, m);
    }
    mean *= (1.0f / KNN);
    float xv = x[n * C_DIM + c];
    scat[g][c] = mean;
    scat[g][64 + c] = mx;
    sx[g][c] = xv;
    __syncthreads();
    float acc = b_lin[c];
#pragma unroll
    for (int j = 0; j < 128; j++) acc = fmaf(scat[g][j], Ws[j * 64 + c], acc);
#pragma unroll
    for (int j = 0; j < 64; j++)
        acc = fmaf(sx[g][j], __ldg(&w_lin[(128 + j) * 64 + c]), acc);
    g_t[n * C_DIM + c] = acc + xv;       // residual before BN2
}

// ---------------- per-channel biased batch stats (deterministic) ----------------
__global__ void k_stats(int which) {
    const float* v = (which == 0) ? g_t : g_wres;
    float* mu = (which == 0) ? g_mu2 : g_mu3;
    float* rs = (which == 0) ? g_rs2 : g_rs3;
    __shared__ float ssum[256], ssq[256];
    int c = blockIdx.x;
    int tid = threadIdx.x;
    float s = 0.f, s2 = 0.f;
    for (int n = tid; n < N_NODES; n += 256) {
        float val = v[n * C_DIM + c];
        s += val;
        s2 = fmaf(val, val, s2);
    }
    ssum[tid] = s; ssq[tid] = s2;
    __syncthreads();
    for (int o = 128; o > 0; o >>= 1) {
        if (tid < o) { ssum[tid] += ssum[tid + o]; ssq[tid] += ssq[tid + o]; }
        __syncthreads();
    }
    if (tid == 0) {
        float m = ssum[0] * (1.0f / N_NODES);
        float var = ssq[0] * (1.0f / N_NODES) - m * m;
        mu[c] = m;
        rs[c] = rsqrtf(var + BN_EPS);
    }
}

// ---------------- K4: y = BN2(t); z = elu(y@w_p1+b1)@w_p2+b2; wres = y+z ----------------
__global__ __launch_bounds__(512) void k_mlp(const float* __restrict__ w_p1,
                                             const float* __restrict__ b_p1,
                                             const float* __restrict__ w_p2,
                                             const float* __restrict__ b_p2,
                                             const float* __restrict__ gamma2,
                                             const float* __restrict__ beta2) {
    __shared__ float w1s[64 * 64], w2s[64 * 64];  // 32KB
    __shared__ float sy[8][64], sa[8][64];        // 4KB
    int tid = threadIdx.x;
    for (int i = tid; i < (64 * 64) / 4; i += 512) {
        ((float4*)w1s)[i] = ((const float4*)w_p1)[i];
        ((float4*)w2s)[i] = ((const float4*)w_p2)[i];
    }
    int g = tid >> 6, c = tid & 63;
    int n = blockIdx.x * 8 + g;
    float y = gamma2[c] * (g_t[n * 64 + c] - g_mu2[c]) * g_rs2[c] + beta2[c];
    sy[g][c] = y;
    __syncthreads();
    float a = b_p1[c];
#pragma unroll
    for (int k2 = 0; k2 < 64; k2++) a = fmaf(sy[g][k2], w1s[k2 * 64 + c], a);
    a = (a > 0.f) ? a : expm1f(a);
    sa[g][c] = a;
    __syncthreads();
    float z = b_p2[c];
#pragma unroll
    for (int k2 = 0; k2 < 64; k2++) z = fmaf(sa[g][k2], w2s[k2 * 64 + c], z);
    g_wres[n * 64 + c] = y + z;
}

// ---------------- K5: out = BN3(wres) ----------------
__global__ void k_bn3(float* __restrict__ out,
                      const float* __restrict__ gamma3,
                      const float* __restrict__ beta3) {
    int i = blockIdx.x * 256 + threadIdx.x;   // over N*C/4 float4s
    float4 wv = ((const float4*)g_wres)[i];
    int cb = (i & 15) * 4;
    float4 o;
    o.x = gamma3[cb + 0] * (wv.x - g_mu3[cb + 0]) * g_rs3[cb + 0] + beta3[cb + 0];
    o.y = gamma3[cb + 1] * (wv.y - g_mu3[cb + 1]) * g_rs3[cb + 1] + beta3[cb + 1];
    o.z = gamma3[cb + 2] * (wv.z - g_mu3[cb + 2]) * g_rs3[cb + 2] + beta3[cb + 2];
    o.w = gamma3[cb + 3] * (wv.w - g_mu3[cb + 3]) * g_rs3[cb + 3] + beta3[cb + 3];
    ((float4*)out)[i] = o;
}

// ---------------- launch ----------------
extern "C" void kernel_launch(void* const* d_in, const int* in_sizes, int n_in,
                              void* d_out, int out_size) {
    const float* x      = (const float*)d_in[0];
    const float* w_s    = (const float*)d_in[1];
    const float* w_h    = (const float*)d_in[2];
    const float* b_h    = (const float*)d_in[3];
    const float* w_lin  = (const float*)d_in[4];
    const float* b_lin  = (const float*)d_in[5];
    const float* w_p1   = (const float*)d_in[6];
    const float* b_p1   = (const float*)d_in[7];
    const float* w_p2   = (const float*)d_in[8];
    const float* b_p2   = (const float*)d_in[9];
    const float* gamma2 = (const float*)d_in[10];
    const float* beta2  = (const float*)d_in[11];
    const float* gamma3 = (const float*)d_in[12];
    const float* beta3  = (const float*)d_in[13];
    float* out = (float*)d_out;

    k_prep<<<N_NODES / 8, 512>>>(x, w_h, b_h, w_s);
    dim3 gknn(N_NODES / KNN_T, NPARTS);
    k_knn<<<gknn, KNN_T>>>();
    k_merge<<<N_NODES / 256, 256>>>();
    k_agglin<<<N_NODES / 8, 512>>>(x, w_lin, b_lin);
    k_stats<<<C_DIM, 256>>>(0);
    k_mlp<<<N_NODES / 8, 512>>>(w_p1, b_p1, w_p2, b_p2, gamma2, beta2);
    k_stats<<<C_DIM, 256>>>(1);
    k_bn3<<<(N_NODES * C_DIM) / 4 / 256, 256>>>(out, gamma3, beta3);
}

// round 2
// speedup vs baseline: 1.3123x; 1.3123x over previous
#include <cuda_runtime.h>
#include <math.h>

#define N_NODES 16384
#define C_DIM   64
#define KNN     40
#define NPARTS  4
#define PART    (N_NODES / NPARTS)     // 4096
#define TILE    1024
#define BUF     20
#define KNN_T   128
#define SBLK    32
#define BN_EPS  1e-5f
#define FBIG    1e30f

// ---------------- scratch (static device globals; no allocation) ----------------
__device__ float4 g_s4[N_NODES];
__device__ float  g_h[N_NODES * C_DIM];
__device__ float  g_partD[NPARTS * KNN * N_NODES];
__device__ int    g_partI[NPARTS * KNN * N_NODES];
__device__ int    g_idx[KNN * N_NODES];
__device__ float  g_ew[KNN * N_NODES];
__device__ float  g_t[N_NODES * C_DIM];
__device__ float  g_wres[N_NODES * C_DIM];
__device__ float  g_ps[2][SBLK][C_DIM], g_pq[2][SBLK][C_DIM];
__device__ float  g_mu2[C_DIM], g_rs2[C_DIM], g_mu3[C_DIM], g_rs3[C_DIM];

// ---------------- K1: h = x@w_h + b_h ; s = x@w_s ----------------
__global__ __launch_bounds__(512) void k_prep(const float* __restrict__ x,
                                              const float* __restrict__ w_h,
                                              const float* __restrict__ b_h,
                                              const float* __restrict__ w_s) {
    __shared__ float whs[C_DIM * C_DIM];
    __shared__ float wss[C_DIM * 4];
    __shared__ float sx[8][C_DIM];
    int tid = threadIdx.x;
    for (int i = tid; i < C_DIM * C_DIM; i += 512) whs[i] = w_h[i];
    if (tid < C_DIM * 3) wss[(tid / 3) * 4 + (tid % 3)] = w_s[tid];
    int g = tid >> 6, c = tid & 63;
    int n = blockIdx.x * 8 + g;
    sx[g][c] = x[n * C_DIM + c];
    __syncthreads();
    float acc = b_h[c];
#pragma unroll
    for (int k2 = 0; k2 < C_DIM; k2++) acc = fmaf(sx[g][k2], whs[k2 * C_DIM + c], acc);
    g_h[n * C_DIM + c] = acc;
    if (c < 4) {
        float sv = 0.f;
        if (c < 3) {
#pragma unroll
            for (int k2 = 0; k2 < C_DIM; k2++) sv = fmaf(sx[g][k2], wss[k2 * 4 + c], sv);
        }
        ((float*)g_s4)[n * 4 + c] = sv;
    }
}

// ---------------- K2: kNN (4-way partitioned scan, buffered insert) ----------------
__device__ __forceinline__ void insert40(float (&bd)[KNN], int (&bi)[KNN],
                                         float cd, int ci, bool want) {
    bool placed = !want;
#pragma unroll
    for (int j = KNN - 1; j >= 1; j--) {
        if (!placed) {
            bool sw = cd < bd[j - 1];
            float pu = bd[j - 1];
            int   iu = bi[j - 1];
            bd[j] = sw ? pu : cd;
            bi[j] = sw ? iu : ci;
            placed = !sw;
        }
        if ((j & 7) == 0) {
            if (__all_sync(0xffffffffu, placed)) return;
        }
    }
    if (!placed) { bd[0] = cd; bi[0] = ci; }
}

__device__ __forceinline__ void flush_buf(float (&bd)[KNN], int (&bi)[KNN],
                                          float (*bufD)[BUF], int (*bufI)[BUF],
                                          int tid, int& cnt) {
    int mx = cnt;
#pragma unroll
    for (int o = 16; o > 0; o >>= 1)
        mx = max(mx, __shfl_xor_sync(0xffffffffu, mx, o));
    for (int e = 0; e < mx; e++) {
        bool act = e < cnt;
        float d = act ? bufD[tid][e] : FBIG;
        int idv = act ? bufI[tid][e] : 0;
        insert40(bd, bi, d, idv, act && (d < bd[KNN - 1]));
    }
    cnt = 0;
}

__global__ __launch_bounds__(KNN_T) void k_knn() {
    __shared__ float4 shp[TILE];            // 16KB
    __shared__ float  bufD[KNN_T][BUF];     // 10KB
    __shared__ int    bufI[KNN_T][BUF];     // 10KB
    int tid = threadIdx.x;
    int q = blockIdx.x * KNN_T + tid;
    int base0 = blockIdx.y * PART;
    float4 qs = g_s4[q];
    float bd[KNN]; int bi[KNN];
#pragma unroll
    for (int j = 0; j < KNN; j++) { bd[j] = FBIG; bi[j] = 0; }
    int cnt = 0;

    for (int t0 = 0; t0 < PART; t0 += TILE) {
#pragma unroll
        for (int j = 0; j < TILE / KNN_T; j++)
            shp[j * KNN_T + tid] = g_s4[base0 + t0 + j * KNN_T + tid];
        __syncthreads();
        for (int j = 0; j < TILE; j += 8) {
#pragma unroll
            for (int u = 0; u < 8; u++) {
                float4 p = shp[j + u];
                float dx = qs.x - p.x, dy = qs.y - p.y, dz = qs.z - p.z;
                float d2 = fmaf(dx, dx, fmaf(dy, dy, dz * dz));
                if (d2 < bd[KNN - 1]) {
                    bufD[tid][cnt] = d2;
                    bufI[tid][cnt] = base0 + t0 + j + u;
                    cnt++;
                }
            }
            if (__any_sync(0xffffffffu, cnt >= BUF - 8))
                flush_buf(bd, bi, bufD, bufI, tid, cnt);
        }
        __syncthreads();
    }
    flush_buf(bd, bi, bufD, bufI, tid, cnt);

    int ob = blockIdx.y * KNN;
#pragma unroll
    for (int j = 0; j < KNN; j++) {
        g_partD[(ob + j) * N_NODES + q] = bd[j];
        g_partI[(ob + j) * N_NODES + q] = bi[j];
    }
}

// ---------------- K2b: 4-way merge of sorted lists; edge weights ----------------
__global__ void k_merge() {
    int q = blockIdx.x * 256 + threadIdx.x;
    int a0 = 0, a1 = 0, a2 = 0, a3 = 0;
#pragma unroll 1
    for (int j = 0; j < KNN; j++) {
        float d0 = g_partD[(0 * KNN + a0) * N_NODES + q];
        float d1 = g_partD[(1 * KNN + a1) * N_NODES + q];
        float d2v = g_partD[(2 * KNN + a2) * N_NODES + q];
        float d3 = g_partD[(3 * KNN + a3) * N_NODES + q];
        // pick min; ties -> lower partition (lower global index range)
        int p = 0; float dm = d0;
        if (d1 < dm) { dm = d1; p = 1; }
        if (d2v < dm) { dm = d2v; p = 2; }
        if (d3 < dm) { dm = d3; p = 3; }
        int ap = (p == 0) ? a0 : (p == 1) ? a1 : (p == 2) ? a2 : a3;
        int idv = g_partI[(p * KNN + ap) * N_NODES + q];
        if (p == 0) a0++; else if (p == 1) a1++; else if (p == 2) a2++; else a3++;
        g_idx[j * N_NODES + q] = idv;
        g_ew[j * N_NODES + q] = expf(-(dm + 1e-6f));
    }
}

// ---------------- K3: gather-aggregate (mean,max) + lin(cat) + residual ----------------
__global__ __launch_bounds__(512) void k_agglin(const float* __restrict__ x,
                                                const float* __restrict__ w_lin,
                                                const float* __restrict__ b_lin) {
    __shared__ float Ws[128 * 64];
    __shared__ float scat[8][128];
    __shared__ float sx[8][64];
    int tid = threadIdx.x;
    for (int i = tid; i < (128 * 64) / 4; i += 512)
        ((float4*)Ws)[i] = ((const float4*)w_lin)[i];
    int g = tid >> 6, c = tid & 63;
    int n = blockIdx.x * 8 + g;
    float mean = 0.f, mx = -FBIG;
#pragma unroll 1
    for (int k2 = 0; k2 < KNN; k2 += 8) {
        int ii[8]; float ww[8];
#pragma unroll
        for (int u = 0; u < 8; u++) {
            ii[u] = g_idx[(k2 + u) * N_NODES + n];
            ww[u] = g_ew[(k2 + u) * N_NODES + n];
        }
#pragma unroll
        for (int u = 0; u < 8; u++) {
            float m = ww[u] * g_h[ii[u] * C_DIM + c];
            mean += m;
            mx = fmaxf(mx, m);
        }
    }
    mean *= (1.0f / KNN);
    float xv = x[n * C_DIM + c];
    scat[g][c] = mean;
    scat[g][64 + c] = mx;
    sx[g][c] = xv;
    __syncthreads();
    float acc = b_lin[c];
#pragma unroll
    for (int j = 0; j < 128; j++) acc = fmaf(scat[g][j], Ws[j * 64 + c], acc);
#pragma unroll
    for (int j = 0; j < 64; j++)
        acc = fmaf(sx[g][j], __ldg(&w_lin[(128 + j) * 64 + c]), acc);
    g_t[n * C_DIM + c] = acc + xv;
}

// ---------------- coalesced deterministic BN stats: partial + final ----------------
__global__ __launch_bounds__(256) void k_stats_part(int which) {
    const float* v = (which == 0) ? g_t : g_wres;
    __shared__ float4 rs_[256], rq_[256];
    int tid = threadIdx.x;
    int cg = tid & 15, ns = tid >> 4;
    float4 s = {0.f, 0.f, 0.f, 0.f}, sq = {0.f, 0.f, 0.f, 0.f};
    int nbase = blockIdx.x * (N_NODES / SBLK);
#pragma unroll 4
    for (int n = nbase + ns; n < nbase + (N_NODES / SBLK); n += 16) {
        float4 val = ((const float4*)v)[n * 16 + cg];
        s.x += val.x; s.y += val.y; s.z += val.z; s.w += val.w;
        sq.x = fmaf(val.x, val.x, sq.x); sq.y = fmaf(val.y, val.y, sq.y);
        sq.z = fmaf(val.z, val.z, sq.z); sq.w = fmaf(val.w, val.w, sq.w);
    }
    rs_[tid] = s; rq_[tid] = sq;
    __syncthreads();
    for (int off = 128; off >= 16; off >>= 1) {
        if (tid < off) {
            float4 a = rs_[tid], b = rs_[tid + off];
            a.x += b.x; a.y += b.y; a.z += b.z; a.w += b.w;
            rs_[tid] = a;
            float4 c = rq_[tid], d = rq_[tid + off];
            c.x += d.x; c.y += d.y; c.z += d.z; c.w += d.w;
            rq_[tid] = c;
        }
        __syncthreads();
    }
    if (tid < 16) {
        float4 a = rs_[tid], b = rq_[tid];
        g_ps[which][blockIdx.x][tid * 4 + 0] = a.x;
        g_ps[which][blockIdx.x][tid * 4 + 1] = a.y;
        g_ps[which][blockIdx.x][tid * 4 + 2] = a.z;
        g_ps[which][blockIdx.x][tid * 4 + 3] = a.w;
        g_pq[which][blockIdx.x][tid * 4 + 0] = b.x;
        g_pq[which][blockIdx.x][tid * 4 + 1] = b.y;
        g_pq[which][blockIdx.x][tid * 4 + 2] = b.z;
        g_pq[which][blockIdx.x][tid * 4 + 3] = b.w;
    }
}

__global__ void k_stats_fin(int which) {
    int c = threadIdx.x;   // 64 threads
    float s = 0.f, s2 = 0.f;
#pragma unroll
    for (int b = 0; b < SBLK; b++) {
        s += g_ps[which][b][c];
        s2 += g_pq[which][b][c];
    }
    float m = s * (1.0f / N_NODES);
    float var = s2 * (1.0f / N_NODES) - m * m;
    if (which == 0) { g_mu2[c] = m; g_rs2[c] = rsqrtf(var + BN_EPS); }
    else            { g_mu3[c] = m; g_rs3[c] = rsqrtf(var + BN_EPS); }
}

// ---------------- K4: y = BN2(t); z = elu(y@w_p1+b1)@w_p2+b2; wres = y+z ----------------
__global__ __launch_bounds__(512) void k_mlp(const float* __restrict__ w_p1,
                                             const float* __restrict__ b_p1,
                                             const float* __restrict__ w_p2,
                                             const float* __restrict__ b_p2,
                                             const float* __restrict__ gamma2,
                                             const float* __restrict__ beta2) {
    __shared__ float w1s[64 * 64], w2s[64 * 64];
    __shared__ float sy[8][64], sa[8][64];
    int tid = threadIdx.x;
    for (int i = tid; i < (64 * 64) / 4; i += 512) {
        ((float4*)w1s)[i] = ((const float4*)w_p1)[i];
        ((float4*)w2s)[i] = ((const float4*)w_p2)[i];
    }
    int g = tid >> 6, c = tid & 63;
    int n = blockIdx.x * 8 + g;
    float y = gamma2[c] * (g_t[n * 64 + c] - g_mu2[c]) * g_rs2[c] + beta2[c];
    sy[g][c] = y;
    __syncthreads();
    float a = b_p1[c];
#pragma unroll
    for (int k2 = 0; k2 < 64; k2++) a = fmaf(sy[g][k2], w1s[k2 * 64 + c], a);
    a = (a > 0.f) ? a : expm1f(a);
    sa[g][c] = a;
    __syncthreads();
    float z = b_p2[c];
#pragma unroll
    for (int k2 = 0; k2 < 64; k2++) z = fmaf(sa[g][k2], w2s[k2 * 64 + c], z);
    g_wres[n * 64 + c] = y + z;
}

// ---------------- K5: out = BN3(wres) ----------------
__global__ void k_bn3(float* __restrict__ out,
                      const float* __restrict__ gamma3,
                      const float* __restrict__ beta3) {
    int i = blockIdx.x * 256 + threadIdx.x;
    float4 wv = ((const float4*)g_wres)[i];
    int cb = (i & 15) * 4;
    float4 o;
    o.x = gamma3[cb + 0] * (wv.x - g_mu3[cb + 0]) * g_rs3[cb + 0] + beta3[cb + 0];
    o.y = gamma3[cb + 1] * (wv.y - g_mu3[cb + 1]) * g_rs3[cb + 1] + beta3[cb + 1];
    o.z = gamma3[cb + 2] * (wv.z - g_mu3[cb + 2]) * g_rs3[cb + 2] + beta3[cb + 2];
    o.w = gamma3[cb + 3] * (wv.w - g_mu3[cb + 3]) * g_rs3[cb + 3] + beta3[cb + 3];
    ((float4*)out)[i] = o;
}

// ---------------- launch ----------------
extern "C" void kernel_launch(void* const* d_in, const int* in_sizes, int n_in,
                              void* d_out, int out_size) {
    const float* x      = (const float*)d_in[0];
    const float* w_s    = (const float*)d_in[1];
    const float* w_h    = (const float*)d_in[2];
    const float* b_h    = (const float*)d_in[3];
    const float* w_lin  = (const float*)d_in[4];
    const float* b_lin  = (const float*)d_in[5];
    const float* w_p1   = (const float*)d_in[6];
    const float* b_p1   = (const float*)d_in[7];
    const float* w_p2   = (const float*)d_in[8];
    const float* b_p2   = (const float*)d_in[9];
    const float* gamma2 = (const float*)d_in[10];
    const float* beta2  = (const float*)d_in[11];
    const float* gamma3 = (const float*)d_in[12];
    const float* beta3  = (const float*)d_in[13];
    float* out = (float*)d_out;

    k_prep<<<N_NODES / 8, 512>>>(x, w_h, b_h, w_s);
    dim3 gknn(N_NODES / KNN_T, NPARTS);
    k_knn<<<gknn, KNN_T>>>();
    k_merge<<<N_NODES / 256, 256>>>();
    k_agglin<<<N_NODES / 8, 512>>>(x, w_lin, b_lin);
    k_stats_part<<<SBLK, 256>>>(0);
    k_stats_fin<<<1, C_DIM>>>(0);
    k_mlp<<<N_NODES / 8, 512>>>(w_p1, b_p1, w_p2, b_p2, gamma2, beta2);
    k_stats_part<<<SBLK, 256>>>(1);
    k_stats_fin<<<1, C_DIM>>>(1);
    k_bn3<<<(N_NODES * C_DIM) / 4 / 256, 256>>>(out, gamma3, beta3);
}